// round 10
// baseline (speedup 1.0000x reference)
#include <cuda_runtime.h>
#include <cuda_fp16.h>
#include <math.h>
#include <stdint.h>

#define B_    8
#define N_    4096
#define CIN_  64
#define COUT_ 128
#define R_    32
#define R3_   32768
#define NG_   8
#define GN_EPS_ 1e-5f

// ---------------- scratch (static device globals; no allocation) -------------
// grid is TRANSPOSED: [b][voxel][ci]  (ci contiguous)
static __device__ float g_grid[B_ * R3_ * CIN_];
static __device__ float g_cnt [B_ * R3_];
static __device__ int   g_vox [B_ * N_];
static __device__ float g_nc  [B_ * N_ * 3];
static __device__ float g_h1  [B_ * COUT_ * R3_];
static __device__ float g_h2  [B_ * COUT_ * R3_];
static __device__ float g_pf  [B_ * COUT_ * N_];
static __device__ float g_mean [B_ * NG_];
static __device__ float g_rstd [B_ * NG_];
static __device__ float g_mean2[B_ * NG_];
static __device__ float g_rstd2[B_ * NG_];
static __device__ float g_sum [B_ * NG_];
static __device__ float g_sum2[B_ * NG_];
// fp16 weights: [tap][ci-chunk32][co 128][ci 32]
static __device__ __half g_w1[27 * 2 * 128 * 32];
static __device__ __half g_w2[27 * 4 * 128 * 32];

// ---------------- mma.sync m16n8k16 fp16 ------------------------------------
#define MMA_F16(dd, a0, a1, a2, a3, b0, b1) \
    asm volatile("mma.sync.aligned.m16n8k16.row.col.f32.f16.f16.f32 " \
        "{%0,%1,%2,%3}, {%4,%5,%6,%7}, {%8,%9}, {%0,%1,%2,%3};" \
        : "+f"((dd)[0]), "+f"((dd)[1]), "+f"((dd)[2]), "+f"((dd)[3]) \
        : "r"(a0), "r"(a1), "r"(a2), "r"(a3), "r"(b0), "r"(b1))

__device__ __forceinline__ void ldsm4(uint32_t* r, uint32_t addr) {
    asm volatile("ldmatrix.sync.aligned.m8n8.x4.shared.b16 {%0,%1,%2,%3}, [%4];"
        : "=r"(r[0]), "=r"(r[1]), "=r"(r[2]), "=r"(r[3]) : "r"(addr));
}
__device__ __forceinline__ uint32_t smem_u32(const void* p) {
    uint32_t a;
    asm("{ .reg .u64 t; cvta.to.shared.u64 t, %1; cvt.u32.u64 %0, t; }" : "=r"(a) : "l"(p));
    return a;
}

// ============================ coords ==========================================
__global__ void coords_kernel(const float* __restrict__ coords,
                              float* __restrict__ nc, int* __restrict__ vox,
                              float* __restrict__ cnt) {
    int b = blockIdx.x, tid = threadIdx.x;
    __shared__ float red[256];
    __shared__ float smean[3];
    __shared__ float sinv;

    float s0 = 0.f, s1 = 0.f, s2 = 0.f;
    for (int n = tid; n < N_; n += 256) {
        const float* c = &coords[(b * N_ + n) * 3];
        s0 += c[0]; s1 += c[1]; s2 += c[2];
    }
    float ss[3] = {s0, s1, s2};
    for (int d = 0; d < 3; d++) {
        red[tid] = ss[d]; __syncthreads();
        for (int st = 128; st > 0; st >>= 1) {
            if (tid < st) red[tid] += red[tid + st];
            __syncthreads();
        }
        if (tid == 0) smean[d] = red[0] * (1.0f / N_);
        __syncthreads();
    }
    float m0 = smean[0], m1 = smean[1], m2 = smean[2];

    float mx = 0.f;
    for (int n = tid; n < N_; n += 256) {
        const float* c = &coords[(b * N_ + n) * 3];
        float dx = c[0] - m0, dy = c[1] - m1, dz = c[2] - m2;
        mx = fmaxf(mx, dx * dx + dy * dy + dz * dz);
    }
    red[tid] = mx; __syncthreads();
    for (int st = 128; st > 0; st >>= 1) {
        if (tid < st) red[tid] = fmaxf(red[tid], red[tid + st]);
        __syncthreads();
    }
    if (tid == 0) sinv = 1.0f / (2.0f * sqrtf(red[0]));
    __syncthreads();
    float inv = sinv;

    for (int n = tid; n < N_; n += 256) {
        const float* c = &coords[(b * N_ + n) * 3];
        float v[3]; int iv[3];
        float cc[3] = {c[0] - m0, c[1] - m1, c[2] - m2};
        #pragma unroll
        for (int d = 0; d < 3; d++) {
            float x = (cc[d] * inv + 0.5f) * (float)R_;
            x = fminf(fmaxf(x, 0.f), (float)(R_ - 1));
            v[d] = x;
            iv[d] = (int)rintf(x);
        }
        nc[(b * N_ + n) * 3 + 0] = v[0];
        nc[(b * N_ + n) * 3 + 1] = v[1];
        nc[(b * N_ + n) * 3 + 2] = v[2];
        int flat = (iv[0] * R_ + iv[1]) * R_ + iv[2];
        vox[b * N_ + n] = flat;
        atomicAdd(&cnt[b * R3_ + flat], 1.0f);
    }
}

// ---------------- weight prep (both convs): fp32 -> fp16 ---------------------
__global__ void wprep2_kernel(const float* __restrict__ w1, const float* __restrict__ w2,
                              __half* __restrict__ o1, __half* __restrict__ o2) {
    int t = blockIdx.x * 256 + threadIdx.x;
    const int N1 = 27 * 128 * CIN_;
    if (t < N1) {
        int ci = t % CIN_;
        int co = (t / CIN_) & 127;
        int tap = t / (CIN_ * 128);
        float v = w1[(co * CIN_ + ci) * 27 + tap];
        int idx = ((tap * (CIN_ >> 5) + (ci >> 5)) * 128 + co) * 32 + (ci & 31);
        o1[idx] = __float2half_rn(v);
    } else {
        t -= N1;
        if (t >= 27 * 128 * COUT_) return;
        int ci = t % COUT_;
        int co = (t / COUT_) & 127;
        int tap = t / (COUT_ * 128);
        float v = w2[(co * COUT_ + ci) * 27 + tap];
        int idx = ((tap * (COUT_ >> 5) + (ci >> 5)) * 128 + co) * 32 + (ci & 31);
        o2[idx] = __float2half_rn(v);
    }
}

// ---------------- scatter (smem transpose -> coalesced atomics) --------------
__global__ void scatter_t_kernel(const float* __restrict__ f,
                                 const int* __restrict__ vox,
                                 float* __restrict__ grid) {
    int b = blockIdx.x >> 6, ng = blockIdx.x & 63;
    int n0 = ng * 64;
    int tid = threadIdx.x;
    __shared__ float buf[64][65];
    #pragma unroll
    for (int k = 0; k < 16; k++) {
        int idx = k * 256 + tid;
        int c = idx >> 6, dn = idx & 63;
        buf[c][dn] = f[((size_t)b * 64 + c) * N_ + n0 + dn];
    }
    __syncthreads();
    #pragma unroll
    for (int k = 0; k < 16; k++) {
        int idx = k * 256 + tid;
        int dn = idx >> 6, c = idx & 63;
        int flat = vox[b * N_ + n0 + dn];
        atomicAdd(&grid[((size_t)b * R3_ + flat) * 64 + c], buf[c][dn]);
    }
}

// ---------------- cleanup (end of run): zero occupied grid cols + cnt --------
__global__ void cleanup_kernel(const int* __restrict__ vox,
                               float* __restrict__ grid, float* __restrict__ cnt) {
    int t = blockIdx.x * 256 + threadIdx.x;   // B*N
    int b = t >> 12;
    int flat = vox[t];
    cnt[b * R3_ + flat] = 0.f;
    float4* g4 = (float4*)&grid[((size_t)b * R3_ + flat) * 64];
    const float4 z = make_float4(0.f, 0.f, 0.f, 0.f);
    #pragma unroll
    for (int k = 0; k < 16; k++) g4[k] = z;
}

// ============================ mma.sync conv3d (fp16) =========================
// CTA: 256 thr = 8 warps. Output tile: [128 co] x [2x2 xy lines x 32 z].
// SMEM: X [16 line tiles][34 z][40 pad] fp16 at 0 (43,520 B)
//       W double buffer [128][40] fp16 per buf at 43,520 (2 x 10,240 B)
//       flags[16] at 64,000 ; rc[512]/sscale+sshift[64] at 64,064
#define LSTRB   2720
#define W_OFF   43520
#define WBUF    10240
#define FLG_OFF 64000
#define RC_OFF  64064
#define CONV_SMEM 66112

__global__ __launch_bounds__(256, 2)
void conv3d_mma_kernel(const float* __restrict__ in,
                       const __half* __restrict__ wgt,
                       const float* __restrict__ bias,
                       float* __restrict__ out, int Cin,
                       const float* __restrict__ cnt,    // conv1: transposed in + 1/cnt
                       const float* __restrict__ gnm, const float* __restrict__ gnrs,
                       const float* __restrict__ gng, const float* __restrict__ gnb,
                       float* __restrict__ gs, float* __restrict__ gs2) {
    extern __shared__ __align__(16) char smem[];
    __half* X = (__half*)smem;
    int* flags = (int*)(smem + FLG_OFF);
    float* rc = (float*)(smem + RC_OFF);
    float* sscale = (float*)(smem + RC_OFF);
    float* sshift = sscale + 32;
    uint32_t sb = smem_u32(smem);
    uint32_t x_u = sb, w_u = sb + W_OFF;

    int tid = threadIdx.x, wid = tid >> 5, lane = tid & 31;
    int bx = blockIdx.x, b = blockIdx.y;
    int x0 = (bx >> 4) * 2, y0 = (bx & 15) * 2;
    int nch = Cin >> 5;
    int line = wid & 3;
    int cobase = (wid >> 2) * 64;
    int g = lane >> 2, t4 = lane & 3;
    bool hc = (cnt != nullptr);

    uint32_t a_off = ((uint32_t)((lane & 7) + ((lane >> 3) & 1) * 8) * 40
                      + (uint32_t)(lane >> 4) * 8) * 2;
    uint32_t b_off = ((uint32_t)((lane & 7) + (lane >> 4) * 8) * 40
                      + (uint32_t)((lane >> 3) & 1) * 8) * 2;

    int j0 = tid, j1 = tid + 256;
    uint32_t wd0 = (uint32_t)(j0 >> 2) * 80 + (uint32_t)(j0 & 3) * 16;
    uint32_t wd1 = (uint32_t)(j1 >> 2) * 80 + (uint32_t)(j1 & 3) * 16;

    if (tid < 16) flags[tid] = hc ? 0 : 1;
    __syncthreads();
    if (hc) {   // per-column reciprocal counts + nonzero flags (conv1)
        for (int i = tid; i < 512; i += 256) {
            int il = i >> 5, z = i & 31;
            int gx = x0 - 1 + (il >> 2), gy = y0 - 1 + (il & 3);
            float c = 0.f;
            if ((unsigned)gx < 32u && (unsigned)gy < 32u)
                c = cnt[(size_t)b * R3_ + gx * 1024 + gy * 32 + z];
            rc[i] = __frcp_rn(fmaxf(c, 1.f));
            if (c > 0.f) flags[il] = 1;
        }
    }

    float d[4][4][4];
    #pragma unroll
    for (int m = 0; m < 4; m++)
        #pragma unroll
        for (int n = 0; n < 4; n++)
            #pragma unroll
            for (int r = 0; r < 4; r++) d[m][n][r] = 0.f;

    for (int ch = 0; ch < nch; ch++) {
        int c0 = ch * 32;
        __syncthreads();                 // prev chunk fully consumed
        if (gng) {                       // conv2: per-chunk GN scale/shift
            if (tid < 32) {
                int cc = c0 + tid;
                int gi = b * NG_ + (cc >> 4);
                float sc = gnrs[gi] * gng[cc];
                sscale[tid] = sc;
                sshift[tid] = gnb[cc] - gnm[gi] * sc;
            }
            __syncthreads();
        }
        // zero z-halo rows
        for (int i = tid; i < 1024; i += 256) {
            int ci = i & 31, r2 = (i >> 5) & 1, il = i >> 6;
            X[il * 1360 + (r2 ? 33 : 0) * 40 + ci] = __float2half_rn(0.f);
        }
        if (hc) {
            // conv1: transposed input [b][voxel][64ci]; 16 lines x 32 z x 8 ci-quads
            for (int i = tid; i < 4096; i += 256) {
                int c4 = i & 7;
                int z  = (i >> 3) & 31;
                int il = i >> 8;
                int gx = x0 - 1 + (il >> 2), gy = y0 - 1 + (il & 3);
                float4 v = make_float4(0.f, 0.f, 0.f, 0.f);
                if ((unsigned)gx < 32u && (unsigned)gy < 32u)
                    v = *(const float4*)&in[((size_t)b * R3_ + gx * 1024 + gy * 32 + z) * 64 + c0 + c4 * 4];
                float r = rc[il * 32 + z];
                int base = il * 1360 + (z + 1) * 40 + c4 * 4;
                *(__half2*)&X[base]     = __floats2half2_rn(v.x * r, v.y * r);
                *(__half2*)&X[base + 2] = __floats2half2_rn(v.z * r, v.w * r);
            }
        } else {
            // conv2: [b][c][voxel] input with fused GN+swish
            for (int i = tid; i < 4096; i += 256) {
                int zq = i & 7, ci = (i >> 3) & 31, il = i >> 8;
                int gx = x0 - 1 + (il >> 2), gy = y0 - 1 + (il & 3);
                float4 v = make_float4(0.f, 0.f, 0.f, 0.f);
                if ((unsigned)gx < 32u && (unsigned)gy < 32u)
                    v = *(const float4*)&in[(((size_t)(b * Cin + c0 + ci) * 32 + gx) * 32 + gy) * 32 + zq * 4];
                float sc = sscale[ci], sh = sshift[ci];
                int base = il * 1360 + (zq * 4 + 1) * 40 + ci;
                #pragma unroll
                for (int j = 0; j < 4; j++) {
                    float y = (&v.x)[j] * sc + sh;
                    y = y / (1.0f + expf(-y));
                    X[base + j * 40] = __float2half_rn(y);
                }
            }
        }
        {
            const uint4* sh4 = (const uint4*)(wgt + (size_t)(0 * nch + ch) * 4096);
            *(uint4*)(smem + W_OFF + wd0) = sh4[j0];
            *(uint4*)(smem + W_OFF + wd1) = sh4[j1];
        }
        __syncthreads();

        for (int tap = 0; tap < 27; tap++) {
            int buf = tap & 1;
            uint4 nh0, nh1;
            bool pre = (tap < 26);
            if (pre) {
                const uint4* sh4 = (const uint4*)(wgt + (size_t)((tap + 1) * nch + ch) * 4096);
                nh0 = sh4[j0]; nh1 = sh4[j1];
            }

            int dz = tap % 3, dyy = (tap / 3) % 3, dxx = tap / 9;
            int il = ((line >> 1) + dxx) * 4 + (line & 1) + dyy;
            if (flags[il]) {
                uint32_t xb = x_u + (uint32_t)il * LSTRB + (uint32_t)dz * 80;
                uint32_t wb = w_u + (uint32_t)buf * WBUF + (uint32_t)cobase * 80;
                #pragma unroll
                for (int k = 0; k < 2; k++) {
                    uint32_t Bf[8];
                    ldsm4(&Bf[0], xb + (uint32_t)k * 32 + b_off);
                    ldsm4(&Bf[4], xb + 1280 + (uint32_t)k * 32 + b_off);
                    #pragma unroll
                    for (int m = 0; m < 4; m++) {
                        uint32_t Af[4];
                        ldsm4(Af, wb + (uint32_t)m * 1280 + (uint32_t)k * 32 + a_off);
                        #pragma unroll
                        for (int n = 0; n < 4; n++)
                            MMA_F16(d[m][n], Af[0], Af[1], Af[2], Af[3], Bf[n * 2], Bf[n * 2 + 1]);
                    }
                }
            }

            if (pre) {
                char* dst = smem + W_OFF + (buf ^ 1) * WBUF;
                *(uint4*)(dst + wd0) = nh0;
                *(uint4*)(dst + wd1) = nh1;
            }
            __syncthreads();
        }
    }

    // epilogue: write out + fused GroupNorm partial stats
    int ox = x0 + (line >> 1), oy = y0 + (line & 1);
    #pragma unroll
    for (int m = 0; m < 4; m++) {
        int co = cobase + m * 16 + g;
        float bv0 = bias[co], bv1 = bias[co + 8];
        float s = 0.f, s2 = 0.f;
        float* p0 = out + ((size_t)(b * COUT_ + co)) * R3_ + ox * 1024 + oy * 32;
        float* p1 = p0 + (size_t)8 * R3_;
        #pragma unroll
        for (int n = 0; n < 4; n++) {
            float v0 = d[m][n][0] + bv0, v1 = d[m][n][1] + bv0;
            float v2 = d[m][n][2] + bv1, v3 = d[m][n][3] + bv1;
            int z = n * 8 + t4 * 2;
            *(float2*)(p0 + z) = make_float2(v0, v1);
            *(float2*)(p1 + z) = make_float2(v2, v3);
            s += v0 + v1 + v2 + v3;
            s2 += v0 * v0 + v1 * v1 + v2 * v2 + v3 * v3;
        }
        #pragma unroll
        for (int off = 16; off > 0; off >>= 1) {
            s += __shfl_xor_sync(0xffffffffu, s, off);
            s2 += __shfl_xor_sync(0xffffffffu, s2, off);
        }
        if (lane == 0) {
            int grp = b * NG_ + (cobase >> 4) + m;
            atomicAdd(&gs[grp], s);
            atomicAdd(&gs2[grp], s2);
        }
    }
}

// ---------------- finalize GN stats (and reset accumulators) -----------------
__global__ void gn_finalize_kernel(float* __restrict__ gs, float* __restrict__ gs2,
                                   float* __restrict__ mean, float* __restrict__ rstd) {
    int i = threadIdx.x;
    const float n = 16.0f * (float)R3_;
    float s = gs[i], s2 = gs2[i];
    float m = s / n;
    mean[i] = m;
    rstd[i] = rsqrtf(s2 / n - m * m + GN_EPS_);
    gs[i] = 0.f; gs2[i] = 0.f;
}

// ---------------- GroupNorm stats (point branch) -----------------------------
__global__ void gn_stats_kernel(const float* __restrict__ x, int S,
                                float* __restrict__ mean, float* __restrict__ rstd) {
    int bg = blockIdx.x;
    const float* p = x + (long)bg * 16 * S;
    int n = 16 * S;
    float s = 0.f, s2 = 0.f;
    for (int i = threadIdx.x; i < n; i += blockDim.x) {
        float v = p[i];
        s += v; s2 += v * v;
    }
    __shared__ float ra[512], rb[512];
    int tid = threadIdx.x;
    ra[tid] = s; rb[tid] = s2; __syncthreads();
    for (int st = 256; st > 0; st >>= 1) {
        if (tid < st) { ra[tid] += ra[tid + st]; rb[tid] += rb[tid + st]; }
        __syncthreads();
    }
    if (tid == 0) {
        float m = ra[0] / (float)n;
        float var = rb[0] / (float)n - m * m;
        mean[bg] = m;
        rstd[bg] = rsqrtf(var + GN_EPS_);
    }
}

__global__ void ptgemm_kernel(const float* __restrict__ f, const float* __restrict__ w,
                              const float* __restrict__ bias, float* __restrict__ pf) {
    int t = blockIdx.x * blockDim.x + threadIdx.x;
    int n = t & (N_ - 1);
    int r = t >> 12;
    int o = (r & 31) * 4;
    int b = r >> 5;
    float a0 = bias[o], a1 = bias[o + 1], a2 = bias[o + 2], a3 = bias[o + 3];
    const float* fb = f + (b * CIN_) * N_ + n;
    const float* w0 = w + o * CIN_;
    #pragma unroll 8
    for (int c = 0; c < CIN_; c++) {
        float fv = fb[c * N_];
        a0 += w0[c] * fv;
        a1 += w0[CIN_ + c] * fv;
        a2 += w0[2 * CIN_ + c] * fv;
        a3 += w0[3 * CIN_ + c] * fv;
    }
    float* op = &pf[(b * COUT_ + o) * N_ + n];
    op[0] = a0; op[N_] = a1; op[2 * N_] = a2; op[3 * N_] = a3;
}

// -------- devoxelize with fused GN+swish(h2) + point-branch GN/swish + add ---
__global__ void final_kernel(const float* __restrict__ nc, const float* __restrict__ h2,
                             const float* __restrict__ pf,
                             const float* __restrict__ g2g, const float* __restrict__ g2b,
                             const float* __restrict__ mean2, const float* __restrict__ rstd2,
                             const float* __restrict__ pgg, const float* __restrict__ pgb,
                             const float* __restrict__ meanp, const float* __restrict__ rstdp,
                             float* __restrict__ out) {
    int t = blockIdx.x * blockDim.x + threadIdx.x;
    int n = t & (N_ - 1);
    int r = t >> 12;
    int o = (r & 31) * 4;
    int b = r >> 5;

    float ncx = nc[(b * N_ + n) * 3 + 0];
    float ncy = nc[(b * N_ + n) * 3 + 1];
    float ncz = nc[(b * N_ + n) * 3 + 2];
    float fx = floorf(ncx), fy = floorf(ncy), fz = floorf(ncz);
    float dx = ncx - fx, dy = ncy - fy, dz = ncz - fz;
    int ix0 = (int)fx, iy0 = (int)fy, iz0 = (int)fz;
    int ix1 = min(ix0 + 1, R_ - 1), iy1 = min(iy0 + 1, R_ - 1), iz1 = min(iz0 + 1, R_ - 1);
    float wx[2] = {1.f - dx, dx}, wy[2] = {1.f - dy, dy}, wz[2] = {1.f - dz, dz};
    int xs[2] = {ix0, ix1}, ys[2] = {iy0, iy1}, zs[2] = {iz0, iz1};

    int gidx = b * NG_ + (o >> 4);
    float m2 = mean2[gidx], rs2 = rstd2[gidx];
    float ga[4], be[4];
    #pragma unroll
    for (int j = 0; j < 4; j++) { ga[j] = g2g[o + j]; be[j] = g2b[o + j]; }

    float dv[4] = {0.f, 0.f, 0.f, 0.f};
    const float* hb = &h2[(size_t)(b * COUT_ + o) * R3_];
    #pragma unroll
    for (int k = 0; k < 8; k++) {
        int kx = k >> 2, ky = (k >> 1) & 1, kz = k & 1;
        float wk = wx[kx] * wy[ky] * wz[kz];
        int id = (xs[kx] * R_ + ys[ky]) * R_ + zs[kz];
        #pragma unroll
        for (int j = 0; j < 4; j++) {
            float y = (hb[(size_t)j * R3_ + id] - m2) * rs2 * ga[j] + be[j];
            dv[j] += wk * (y / (1.0f + expf(-y)));
        }
    }

    float mp = meanp[gidx], rsp = rstdp[gidx];
    const float* pp = &pf[(b * COUT_ + o) * N_ + n];
    float* op = &out[(b * COUT_ + o) * N_ + n];
    #pragma unroll
    for (int j = 0; j < 4; j++) {
        int c = o + j;
        float y = (pp[j * N_] - mp) * rsp * pgg[c] + pgb[c];
        op[j * N_] = dv[j] + y / (1.0f + expf(-y));
    }
}

// ---------------- host launcher ----------------------------------------------
extern "C" void kernel_launch(void* const* d_in, const int* in_sizes, int n_in,
                              void* d_out, int out_size) {
    const float* features = (const float*)d_in[0];
    const float* coords   = (const float*)d_in[1];
    const float* c1w = (const float*)d_in[2];
    const float* c1b = (const float*)d_in[3];
    const float* g1g = (const float*)d_in[4];
    const float* g1b = (const float*)d_in[5];
    const float* c2w = (const float*)d_in[6];
    const float* c2b = (const float*)d_in[7];
    const float* g2g = (const float*)d_in[8];
    const float* g2b = (const float*)d_in[9];
    const float* ptw = (const float*)d_in[10];
    const float* ptb = (const float*)d_in[11];
    const float* pgg = (const float*)d_in[12];
    const float* pgb = (const float*)d_in[13];
    float* out = (float*)d_out;

    float *grid_p, *cnt_p, *h1, *h2, *pf, *nc;
    float *mean_p, *rstd_p, *mean2_p, *rstd2_p, *gs, *gs2;
    int* vox_p;
    __half *w1, *w2;
    cudaGetSymbolAddress((void**)&grid_p, g_grid);
    cudaGetSymbolAddress((void**)&cnt_p, g_cnt);
    cudaGetSymbolAddress((void**)&vox_p, g_vox);
    cudaGetSymbolAddress((void**)&nc, g_nc);
    cudaGetSymbolAddress((void**)&h1, g_h1);
    cudaGetSymbolAddress((void**)&h2, g_h2);
    cudaGetSymbolAddress((void**)&pf, g_pf);
    cudaGetSymbolAddress((void**)&mean_p, g_mean);
    cudaGetSymbolAddress((void**)&rstd_p, g_rstd);
    cudaGetSymbolAddress((void**)&mean2_p, g_mean2);
    cudaGetSymbolAddress((void**)&rstd2_p, g_rstd2);
    cudaGetSymbolAddress((void**)&gs, g_sum);
    cudaGetSymbolAddress((void**)&gs2, g_sum2);
    cudaGetSymbolAddress((void**)&w1, g_w1);
    cudaGetSymbolAddress((void**)&w2, g_w2);

    cudaFuncSetAttribute(conv3d_mma_kernel,
                         cudaFuncAttributeMaxDynamicSharedMemorySize, CONV_SMEM);

    // cnt/grid/gs start zeroed (static init on first run; cleanup at end of
    // each run restores that invariant for every graph replay).
    coords_kernel<<<B_, 256>>>(coords, nc, vox_p, cnt_p);                              // 1
    wprep2_kernel<<<(27 * 128 * (CIN_ + COUT_) + 255) / 256, 256>>>(c1w, c2w, w1, w2); // 2
    scatter_t_kernel<<<B_ * 64, 256>>>(features, vox_p, grid_p);                       // 3
    conv3d_mma_kernel<<<dim3(256, 8), 256, CONV_SMEM>>>(grid_p, w1, c1b, h1, CIN_,
        cnt_p, nullptr, nullptr, nullptr, nullptr, gs, gs2);                           // 4 <- ncu
    gn_finalize_kernel<<<1, B_ * NG_>>>(gs, gs2, mean_p, rstd_p);                      // 5
    conv3d_mma_kernel<<<dim3(256, 8), 256, CONV_SMEM>>>(h1, w2, c2b, h2, COUT_,
        nullptr, mean_p, rstd_p, g1g, g1b, gs, gs2);                                   // 6
    gn_finalize_kernel<<<1, B_ * NG_>>>(gs, gs2, mean2_p, rstd2_p);                    // 7
    ptgemm_kernel<<<4096, 256>>>(features, ptw, ptb, pf);                              // 8
    gn_stats_kernel<<<B_ * NG_, 512>>>(pf, N_, mean_p, rstd_p);                        // 9
    final_kernel<<<4096, 256>>>(nc, h2, pf, g2g, g2b, mean2_p, rstd2_p,
                                pgg, pgb, mean_p, rstd_p, out);                        // 10
    cleanup_kernel<<<B_ * N_ / 256, 256>>>(vox_p, grid_p, cnt_p);                      // 11
}